// round 14
// baseline (speedup 1.0000x reference)
#include <cuda_runtime.h>
#include <cuda_fp16.h>
#include <math.h>

#define NNODES 100000
#define EDGES  3200000
#define HDIM   128
#define EDIM   16
#define PTYPES 6
#define CAP    96     // bucket slots per row; Poisson(32) max-degree ~65

// ---- __device__ scratch (allocations are banned) ----
__device__ int    g_cnt[NNODES];          // per-row cursor (zeroed each launch)
__device__ int    g_bkt[NNODES * CAP];    // packed (col | ptype<<24), 38.4 MB
__device__ int    g_ovf;                  // spill count
__device__ int    g_sp_row[EDGES];        // spill rows (adversarial inputs only)
__device__ int    g_sp_pk[EDGES];         // spill packed entries
__device__ __half g_kh[NNODES * HDIM];    // fp16 k     (25.6 MB)
__device__ __half g_vh[NNODES * HDIM];    // fp16 v     (25.6 MB)
__device__ __half g_eh[NNODES * EDIM];    // fp16 eigs   (3.2 MB)
__device__ float  g_pexp[PTYPES];
__device__ float  g_expl;

// ---- packed f32x2 helpers (sm_103a: fma.rn.f32x2 is PTX-only, no C++ path) ----
__device__ __forceinline__ unsigned long long packf2(float a, float b) {
    unsigned long long r;
    asm("mov.b64 %0, {%1, %2};" : "=l"(r) : "f"(a), "f"(b));
    return r;
}
__device__ __forceinline__ unsigned long long h2tof2p(unsigned h) {
    __half2 hh = *reinterpret_cast<__half2*>(&h);
    float2 f = __half22float2(hh);
    return packf2(f.x, f.y);
}
__device__ __forceinline__ void fma2(unsigned long long& d,
                                     unsigned long long a, unsigned long long b) {
    asm("fma.rn.f32x2 %0, %1, %2, %0;" : "+l"(d) : "l"(a), "l"(b));
}
__device__ __forceinline__ float2 unpackf2(unsigned long long p) {
    float2 f;
    asm("mov.b64 {%0, %1}, %2;" : "=f"(f.x), "=f"(f.y) : "l"(p));
    return f;
}

// ---------------------------------------------------------------------------
// 0) zero: cursors + spill counter + exp tables (fast, tiny)
// ---------------------------------------------------------------------------
__global__ void k_zero(const float* __restrict__ lambda0,
                       const float* __restrict__ path_w, int n_nodes) {
    int tid = blockIdx.x * blockDim.x + threadIdx.x;
    int stride = gridDim.x * blockDim.x;
    for (int i = tid; i < n_nodes; i += stride) g_cnt[i] = 0;
    if (tid < PTYPES) g_pexp[tid] = expf(path_w[tid]);
    if (tid == 0) { g_expl = expf(lambda0[0]); g_ovf = 0; }
}

// ---------------------------------------------------------------------------
// 1) fat work kernel: warps 0-3 convert fp32->fp16 (DRAM-bound),
//    warps 4-7 scatter edges into buckets (atomic/latency-bound). Independent.
// ---------------------------------------------------------------------------
__device__ __forceinline__ void bkt_put(int row, int pk) {
    int pos = atomicAdd(&g_cnt[row], 1);
    if (pos < CAP) {
        __stcs(&g_bkt[row * CAP + pos], pk);
    } else {                          // adversarial-degree spill
        int s = atomicAdd(&g_ovf, 1);
        g_sp_row[s] = row;
        g_sp_pk[s]  = pk;
    }
}

__global__ void k_work(const float* __restrict__ k,
                       const float* __restrict__ v,
                       const float* __restrict__ eigs,
                       const int*   __restrict__ indices,
                       const int*   __restrict__ ptype,
                       int n_nodes, int n_edges) {
    int w = threadIdx.x >> 5;
    if (w < 4) {
        // ---- conversion half ----
        int tid = blockIdx.x * 128 + (threadIdx.x & 127);
        int stride = gridDim.x * 128;
        int nk4 = n_nodes * (HDIM / 4);
        for (int i = tid; i < nk4; i += stride) {
            float4 f = __ldcs(reinterpret_cast<const float4*>(k) + i);
            __half2 lo = __floats2half2_rn(f.x, f.y);
            __half2 hi = __floats2half2_rn(f.z, f.w);
            uint2 o;
            o.x = *reinterpret_cast<unsigned*>(&lo);
            o.y = *reinterpret_cast<unsigned*>(&hi);
            reinterpret_cast<uint2*>(g_kh)[i] = o;
        }
        for (int i = tid; i < nk4; i += stride) {
            float4 f = __ldcs(reinterpret_cast<const float4*>(v) + i);
            __half2 lo = __floats2half2_rn(f.x, f.y);
            __half2 hi = __floats2half2_rn(f.z, f.w);
            uint2 o;
            o.x = *reinterpret_cast<unsigned*>(&lo);
            o.y = *reinterpret_cast<unsigned*>(&hi);
            reinterpret_cast<uint2*>(g_vh)[i] = o;
        }
        int ne4 = n_nodes * (EDIM / 4);
        for (int i = tid; i < ne4; i += stride) {
            float4 f = __ldcs(reinterpret_cast<const float4*>(eigs) + i);
            __half2 lo = __floats2half2_rn(f.x, f.y);
            __half2 hi = __floats2half2_rn(f.z, f.w);
            uint2 o;
            o.x = *reinterpret_cast<unsigned*>(&lo);
            o.y = *reinterpret_cast<unsigned*>(&hi);
            reinterpret_cast<uint2*>(g_eh)[i] = o;
        }
    } else {
        // ---- scatter half: 8 edges per group ----
        int tid = blockIdx.x * 128 + (threadIdx.x - 128);
        int stride = gridDim.x * 128;
        int ne8 = n_edges / 8;
        for (int t = tid; t < ne8; t += stride) {
            int4 r0 = __ldcs(reinterpret_cast<const int4*>(indices) + t * 2);
            int4 r1 = __ldcs(reinterpret_cast<const int4*>(indices) + t * 2 + 1);
            int4 c0 = __ldcs(reinterpret_cast<const int4*>(indices + n_edges) + t * 2);
            int4 c1 = __ldcs(reinterpret_cast<const int4*>(indices + n_edges) + t * 2 + 1);
            int4 p0 = __ldcs(reinterpret_cast<const int4*>(ptype) + t * 2);
            int4 p1 = __ldcs(reinterpret_cast<const int4*>(ptype) + t * 2 + 1);
            bkt_put(r0.x, c0.x | (p0.x << 24));
            bkt_put(r0.y, c0.y | (p0.y << 24));
            bkt_put(r0.z, c0.z | (p0.z << 24));
            bkt_put(r0.w, c0.w | (p0.w << 24));
            bkt_put(r1.x, c1.x | (p1.x << 24));
            bkt_put(r1.y, c1.y | (p1.y << 24));
            bkt_put(r1.z, c1.z | (p1.z << 24));
            bkt_put(r1.w, c1.w | (p1.w << 24));
        }
        if (blockIdx.x == 0 && threadIdx.x == 128) {   // <8 leftover edges
            for (int e = ne8 * 8; e < n_edges; e++) {
                int row = __ldg(indices + e);
                int col = __ldg(indices + n_edges + e);
                int pt  = __ldg(ptype + e);
                bkt_put(row, col | (pt << 24));
            }
        }
    }
}

// ---------------------------------------------------------------------------
// 2) fused: warp per row, half-warp per edge, one sweep, 4 edges/iter.
//    shfl_xor butterfly for the score reduction (sm_103 has no redux.f32);
//    fma.rn.f32x2 packed accumulation halves the accum FMA count.
// ---------------------------------------------------------------------------
__global__ void __launch_bounds__(256)
k_fused(const float* __restrict__ q, float* __restrict__ out, int n_nodes) {
    __shared__ float s_pexp[PTYPES];
    if (threadIdx.x < PTYPES) s_pexp[threadIdx.x] = g_pexp[threadIdx.x];
    __syncthreads();

    int warp = (blockIdx.x * blockDim.x + threadIdx.x) >> 5;
    int lane = threadIdx.x & 31;
    if (warp >= n_nodes) return;
    const int row  = warp;
    const int half = lane >> 4;
    const int hl   = lane & 15;
    const int cnt = g_cnt[row];
    const int deg = cnt < CAP ? cnt : CAP;
    const int beg = row * CAP;
    const int end = beg + deg;
    const int ovf = g_ovf;            // 0 for the bench input

    unsigned long long a0[4] = {0,0,0,0};   // sum e0_j * v_j   (f32x2 pairs)
    unsigned long long a1[4] = {0,0,0,0};   // sum pw_j * v_j
    float d0 = 0.f, d1 = 0.f;
    float res[8];

    if (deg > 0 || ovf > 0) {
        const float inv_sqrt_h = 0.08838834764831845f;  // 1/sqrt(128)
        const float* qrow = q + (size_t)row * HDIM + hl * 8;
        float4 qa = __ldcs(reinterpret_cast<const float4*>(qrow));
        float4 qb = __ldcs(reinterpret_cast<const float4*>(qrow) + 1);
        unsigned long long qp[4];
        qp[0] = packf2(qa.x * inv_sqrt_h, qa.y * inv_sqrt_h);
        qp[1] = packf2(qa.z * inv_sqrt_h, qa.w * inv_sqrt_h);
        qp[2] = packf2(qb.x * inv_sqrt_h, qb.y * inv_sqrt_h);
        qp[3] = packf2(qb.z * inv_sqrt_h, qb.w * inv_sqrt_h);
        float er = g_expl * __half2float(__ldg(g_eh + (size_t)row * EDIM + hl));

        int j = beg;
        for (; j + 4 <= end; j += 4) {
            int j0 = j + half;
            int j1 = j + 2 + half;
            int pk0 = __ldcs(g_bkt + j0);
            int pk1 = __ldcs(g_bkt + j1);
            int c0 = pk0 & 0xFFFFFF, c1 = pk1 & 0xFFFFFF;
            uint4 kr0 = __ldg(reinterpret_cast<const uint4*>(g_kh + (size_t)c0 * HDIM + hl * 8));
            uint4 kr1 = __ldg(reinterpret_cast<const uint4*>(g_kh + (size_t)c1 * HDIM + hl * 8));
            uint4 vr0 = __ldg(reinterpret_cast<const uint4*>(g_vh + (size_t)c0 * HDIM + hl * 8));
            uint4 vr1 = __ldg(reinterpret_cast<const uint4*>(g_vh + (size_t)c1 * HDIM + hl * 8));
            float ec0 = __half2float(__ldg(g_eh + (size_t)c0 * EDIM + hl));
            float ec1 = __half2float(__ldg(g_eh + (size_t)c1 * EDIM + hl));

            unsigned long long zp0 = 0ull, zp1 = 0ull;
            fma2(zp0, h2tof2p(kr0.x), qp[0]);
            fma2(zp0, h2tof2p(kr0.y), qp[1]);
            fma2(zp0, h2tof2p(kr0.z), qp[2]);
            fma2(zp0, h2tof2p(kr0.w), qp[3]);
            fma2(zp1, h2tof2p(kr1.x), qp[0]);
            fma2(zp1, h2tof2p(kr1.y), qp[1]);
            fma2(zp1, h2tof2p(kr1.z), qp[2]);
            fma2(zp1, h2tof2p(kr1.w), qp[3]);
            float2 zf0 = unpackf2(zp0);
            float2 zf1 = unpackf2(zp1);
            float z0 = zf0.x + zf0.y + er * ec0;
            float z1 = zf1.x + zf1.y + er * ec1;
            #pragma unroll
            for (int o = 8; o > 0; o >>= 1) {
                z0 += __shfl_xor_sync(0xffffffffu, z0, o);
                z1 += __shfl_xor_sync(0xffffffffu, z1, o);
            }

            float e00 = __expf(z0);
            float e01 = __expf(z1);
            float pw0 = s_pexp[((unsigned)pk0) >> 24];
            float pw1 = s_pexp[((unsigned)pk1) >> 24];
            d0 += e00 + e01;
            d1 += pw0 + pw1;

            unsigned long long vp0[4], vp1[4];
            vp0[0] = h2tof2p(vr0.x); vp0[1] = h2tof2p(vr0.y);
            vp0[2] = h2tof2p(vr0.z); vp0[3] = h2tof2p(vr0.w);
            vp1[0] = h2tof2p(vr1.x); vp1[1] = h2tof2p(vr1.y);
            vp1[2] = h2tof2p(vr1.z); vp1[3] = h2tof2p(vr1.w);
            unsigned long long e0p = packf2(e00, e00);
            unsigned long long e1p = packf2(e01, e01);
            unsigned long long p0p = packf2(pw0, pw0);
            unsigned long long p1p = packf2(pw1, pw1);
            #pragma unroll
            for (int i = 0; i < 4; i++) {
                fma2(a0[i], vp0[i], e0p);
                fma2(a0[i], vp1[i], e1p);
                fma2(a1[i], vp0[i], p0p);
                fma2(a1[i], vp1[i], p1p);
            }
        }
        // tail: up to 3 edges, 2 per step with per-half predication
        for (; j < end; j += 2) {
            int jj = j + half;
            bool valid = jj < end;
            int pk0 = __ldcs(g_bkt + (valid ? jj : beg));
            int c0 = pk0 & 0xFFFFFF;
            uint4 kr0 = __ldg(reinterpret_cast<const uint4*>(g_kh + (size_t)c0 * HDIM + hl * 8));
            uint4 vr0 = __ldg(reinterpret_cast<const uint4*>(g_vh + (size_t)c0 * HDIM + hl * 8));
            float ec0 = __half2float(__ldg(g_eh + (size_t)c0 * EDIM + hl));
            unsigned long long zp0 = 0ull;
            fma2(zp0, h2tof2p(kr0.x), qp[0]);
            fma2(zp0, h2tof2p(kr0.y), qp[1]);
            fma2(zp0, h2tof2p(kr0.z), qp[2]);
            fma2(zp0, h2tof2p(kr0.w), qp[3]);
            float2 zf0 = unpackf2(zp0);
            float z0 = zf0.x + zf0.y + er * ec0;
            #pragma unroll
            for (int o = 8; o > 0; o >>= 1)
                z0 += __shfl_xor_sync(0xffffffffu, z0, o);
            float e00 = valid ? __expf(z0) : 0.f;
            float pw0 = valid ? s_pexp[((unsigned)pk0) >> 24] : 0.f;
            d0 += e00;
            d1 += pw0;
            unsigned long long e0p = packf2(e00, e00);
            unsigned long long p0p = packf2(pw0, pw0);
            unsigned long long vp0[4];
            vp0[0] = h2tof2p(vr0.x); vp0[1] = h2tof2p(vr0.y);
            vp0[2] = h2tof2p(vr0.z); vp0[3] = h2tof2p(vr0.w);
            #pragma unroll
            for (int i = 0; i < 4; i++) {
                fma2(a0[i], vp0[i], e0p);
                fma2(a1[i], vp0[i], p0p);
            }
        }

        // spill entries (only when a row exceeded CAP; never for bench input)
        for (int s = 0; s < ovf; s++) {
            if (g_sp_row[s] != row) continue;
            int pk0 = g_sp_pk[s];
            int c0 = pk0 & 0xFFFFFF;
            uint4 kr0 = __ldg(reinterpret_cast<const uint4*>(g_kh + (size_t)c0 * HDIM + hl * 8));
            uint4 vr0 = __ldg(reinterpret_cast<const uint4*>(g_vh + (size_t)c0 * HDIM + hl * 8));
            float ec0 = __half2float(__ldg(g_eh + (size_t)c0 * EDIM + hl));
            unsigned long long zp0 = 0ull;
            fma2(zp0, h2tof2p(kr0.x), qp[0]);
            fma2(zp0, h2tof2p(kr0.y), qp[1]);
            fma2(zp0, h2tof2p(kr0.z), qp[2]);
            fma2(zp0, h2tof2p(kr0.w), qp[3]);
            float2 zf0 = unpackf2(zp0);
            float z0 = zf0.x + zf0.y + er * ec0;
            #pragma unroll
            for (int o = 8; o > 0; o >>= 1)
                z0 += __shfl_xor_sync(0xffffffffu, z0, o);
            bool act = (half == 0);          // count each spill edge once
            float e00 = act ? __expf(z0) : 0.f;
            float pw0 = act ? s_pexp[((unsigned)pk0) >> 24] : 0.f;
            d0 += e00;
            d1 += pw0;
            unsigned long long e0p = packf2(e00, e00);
            unsigned long long p0p = packf2(pw0, pw0);
            unsigned long long vp0[4];
            vp0[0] = h2tof2p(vr0.x); vp0[1] = h2tof2p(vr0.y);
            vp0[2] = h2tof2p(vr0.z); vp0[3] = h2tof2p(vr0.w);
            #pragma unroll
            for (int i = 0; i < 4; i++) {
                fma2(a0[i], vp0[i], e0p);
                fma2(a1[i], vp0[i], p0p);
            }
        }

        // combine halves and normalize
        d0 += __shfl_xor_sync(0xffffffffu, d0, 16);
        d1 += __shfl_xor_sync(0xffffffffu, d1, 16);
        float i0 = (d0 != 0.f) ? 0.5f / d0 : 0.f;
        float i1 = (d1 != 0.f) ? 0.5f / d1 : 0.f;
        #pragma unroll
        for (int i = 0; i < 4; i++) {
            float2 f0 = unpackf2(a0[i]);
            float2 f1 = unpackf2(a1[i]);
            float r0 = f0.x + __shfl_xor_sync(0xffffffffu, f0.x, 16);
            float r1 = f0.y + __shfl_xor_sync(0xffffffffu, f0.y, 16);
            float s0 = f1.x + __shfl_xor_sync(0xffffffffu, f1.x, 16);
            float s1 = f1.y + __shfl_xor_sync(0xffffffffu, f1.y, 16);
            res[2*i]   = i0 * r0 + i1 * s0;
            res[2*i+1] = i0 * r1 + i1 * s1;
        }
    } else {
        #pragma unroll
        for (int i = 0; i < 8; i++) res[i] = 0.f;
    }

    if (half == 0) {
        float4* o = reinterpret_cast<float4*>(out + (size_t)row * HDIM + hl * 8);
        __stcs(o,     make_float4(res[0], res[1], res[2], res[3]));
        __stcs(o + 1, make_float4(res[4], res[5], res[6], res[7]));
    }
}

// ---------------------------------------------------------------------------
extern "C" void kernel_launch(void* const* d_in, const int* in_sizes, int n_in,
                              void* d_out, int out_size) {
    const float* q       = (const float*)d_in[0];
    const float* k       = (const float*)d_in[1];
    const float* v       = (const float*)d_in[2];
    const float* eigs    = (const float*)d_in[3];
    const float* lambda0 = (const float*)d_in[4];
    const float* path_w  = (const float*)d_in[5];
    const int*   indices = (const int*)d_in[6];
    const int*   ptype   = (const int*)d_in[7];
    float*       out     = (float*)d_out;

    int n_edges = in_sizes[6] / 2;
    int n_nodes = in_sizes[0] / HDIM;
    if (n_edges > EDGES)  n_edges = EDGES;
    if (n_nodes > NNODES) n_nodes = NNODES;

    int rb = (n_nodes * 32 + 255) / 256;

    k_zero<<<512, 256>>>(lambda0, path_w, n_nodes);
    k_work<<<2048, 256>>>(k, v, eigs, indices, ptype, n_nodes, n_edges);
    k_fused<<<rb, 256>>>(q, out, n_nodes);
}

// round 15
// speedup vs baseline: 1.1335x; 1.1335x over previous
#include <cuda_runtime.h>
#include <cuda_fp16.h>
#include <math.h>

#define NNODES 100000
#define EDGES  3200000
#define HDIM   128
#define EDIM   16
#define PTYPES 6
#define CAP    96       // bucket slots per row; Poisson(32) max-degree ~65
#define CONVB  1024     // blocks doing fp16 conversion in k_work

// ---- __device__ scratch (allocations are banned) ----
__device__ int    g_cnt[NNODES];          // per-row cursor (zeroed each launch)
__device__ int    g_bkt[NNODES * CAP];    // packed (col | ptype<<24), 38.4 MB
__device__ int    g_ovf;                  // spill count
__device__ int    g_sp_row[EDGES];        // spill rows (adversarial inputs only)
__device__ int    g_sp_pk[EDGES];         // spill packed entries
__device__ __half g_kh[NNODES * HDIM];    // fp16 k     (25.6 MB)
__device__ __half g_vh[NNODES * HDIM];    // fp16 v     (25.6 MB)
__device__ __half g_eh[NNODES * EDIM];    // fp16 eigs   (3.2 MB)
__device__ float  g_pexp[PTYPES];
__device__ float  g_expl;

// ---------------------------------------------------------------------------
// 0) zero: cursors + spill counter + exp tables (must precede scatter atomics)
// ---------------------------------------------------------------------------
__global__ void k_zero(const float* __restrict__ lambda0,
                       const float* __restrict__ path_w, int n_nodes) {
    int tid = blockIdx.x * blockDim.x + threadIdx.x;
    int stride = gridDim.x * blockDim.x;
    for (int i = tid; i < n_nodes; i += stride) g_cnt[i] = 0;
    if (tid < PTYPES) g_pexp[tid] = expf(path_w[tid]);
    if (tid == 0) { g_expl = expf(lambda0[0]); g_ovf = 0; }
}

// ---------------------------------------------------------------------------
// 1) block-specialized work kernel:
//    blocks [0, CONVB)        : fp32 -> fp16 conversion (DRAM-streaming)
//    blocks [CONVB, CONVB+eb8): bucket scatter (atomic/latency)
//    Roles are whole blocks -> no divergence; both co-scheduled across SMs.
// ---------------------------------------------------------------------------
__device__ __forceinline__ void bkt_put(int row, int pk) {
    int pos = atomicAdd(&g_cnt[row], 1);
    if (pos < CAP) {
        __stcs(&g_bkt[row * CAP + pos], pk);
    } else {                          // adversarial-degree spill
        int s = atomicAdd(&g_ovf, 1);
        g_sp_row[s] = row;
        g_sp_pk[s]  = pk;
    }
}

__global__ void k_work(const float* __restrict__ k,
                       const float* __restrict__ v,
                       const float* __restrict__ eigs,
                       const int*   __restrict__ indices,
                       const int*   __restrict__ ptype,
                       int n_nodes, int n_edges) {
    if (blockIdx.x < CONVB) {
        // ---- conversion role (R12 prep loops, grid-strided over CONVB blocks) ----
        int tid = blockIdx.x * blockDim.x + threadIdx.x;
        int stride = CONVB * blockDim.x;
        int nk4 = n_nodes * (HDIM / 4);
        for (int i = tid; i < nk4; i += stride) {
            float4 f = __ldcs(reinterpret_cast<const float4*>(k) + i);
            __half2 lo = __floats2half2_rn(f.x, f.y);
            __half2 hi = __floats2half2_rn(f.z, f.w);
            uint2 o;
            o.x = *reinterpret_cast<unsigned*>(&lo);
            o.y = *reinterpret_cast<unsigned*>(&hi);
            reinterpret_cast<uint2*>(g_kh)[i] = o;
        }
        for (int i = tid; i < nk4; i += stride) {
            float4 f = __ldcs(reinterpret_cast<const float4*>(v) + i);
            __half2 lo = __floats2half2_rn(f.x, f.y);
            __half2 hi = __floats2half2_rn(f.z, f.w);
            uint2 o;
            o.x = *reinterpret_cast<unsigned*>(&lo);
            o.y = *reinterpret_cast<unsigned*>(&hi);
            reinterpret_cast<uint2*>(g_vh)[i] = o;
        }
        int ne4 = n_nodes * (EDIM / 4);
        for (int i = tid; i < ne4; i += stride) {
            float4 f = __ldcs(reinterpret_cast<const float4*>(eigs) + i);
            __half2 lo = __floats2half2_rn(f.x, f.y);
            __half2 hi = __floats2half2_rn(f.z, f.w);
            uint2 o;
            o.x = *reinterpret_cast<unsigned*>(&lo);
            o.y = *reinterpret_cast<unsigned*>(&hi);
            reinterpret_cast<uint2*>(g_eh)[i] = o;
        }
    } else {
        // ---- scatter role (R12 scatter, 8 edges/thread, direct index) ----
        int t = (blockIdx.x - CONVB) * blockDim.x + threadIdx.x;
        int base = t * 8;
        if (base + 8 <= n_edges) {
            int4 r0 = __ldcs(reinterpret_cast<const int4*>(indices) + t * 2);
            int4 r1 = __ldcs(reinterpret_cast<const int4*>(indices) + t * 2 + 1);
            int4 c0 = __ldcs(reinterpret_cast<const int4*>(indices + n_edges) + t * 2);
            int4 c1 = __ldcs(reinterpret_cast<const int4*>(indices + n_edges) + t * 2 + 1);
            int4 p0 = __ldcs(reinterpret_cast<const int4*>(ptype) + t * 2);
            int4 p1 = __ldcs(reinterpret_cast<const int4*>(ptype) + t * 2 + 1);
            bkt_put(r0.x, c0.x | (p0.x << 24));
            bkt_put(r0.y, c0.y | (p0.y << 24));
            bkt_put(r0.z, c0.z | (p0.z << 24));
            bkt_put(r0.w, c0.w | (p0.w << 24));
            bkt_put(r1.x, c1.x | (p1.x << 24));
            bkt_put(r1.y, c1.y | (p1.y << 24));
            bkt_put(r1.z, c1.z | (p1.z << 24));
            bkt_put(r1.w, c1.w | (p1.w << 24));
        } else if (base < n_edges) {
            for (int e = base; e < n_edges; e++) {
                int row = __ldg(indices + e);
                int col = __ldg(indices + n_edges + e);
                int pt  = __ldg(ptype + e);
                bkt_put(row, col | (pt << 24));
            }
        }
    }
}

// ---------------------------------------------------------------------------
// 2) fused (R12 form, measured ~220us): warp per row, half-warp per edge,
//    one sweep, 4 edges/iter, predicated 2-edge tail.
// ---------------------------------------------------------------------------
__device__ __forceinline__ float dot8h(float4 qa, float4 qb, uint4 kr) {
    float2 k0 = __half22float2(*reinterpret_cast<__half2*>(&kr.x));
    float2 k1 = __half22float2(*reinterpret_cast<__half2*>(&kr.y));
    float2 k2 = __half22float2(*reinterpret_cast<__half2*>(&kr.z));
    float2 k3 = __half22float2(*reinterpret_cast<__half2*>(&kr.w));
    return qa.x * k0.x + qa.y * k0.y + qa.z * k1.x + qa.w * k1.y
         + qb.x * k2.x + qb.y * k2.y + qb.z * k3.x + qb.w * k3.y;
}

__global__ void __launch_bounds__(256)
k_fused(const float* __restrict__ q, float* __restrict__ out, int n_nodes) {
    __shared__ float s_pexp[PTYPES];
    if (threadIdx.x < PTYPES) s_pexp[threadIdx.x] = g_pexp[threadIdx.x];
    __syncthreads();

    int warp = (blockIdx.x * blockDim.x + threadIdx.x) >> 5;
    int lane = threadIdx.x & 31;
    if (warp >= n_nodes) return;
    const int row  = warp;
    const int half = lane >> 4;
    const int hl   = lane & 15;
    const int cnt = g_cnt[row];
    const int deg = cnt < CAP ? cnt : CAP;
    const int beg = row * CAP;
    const int end = beg + deg;
    const int ovf = g_ovf;            // 0 for the bench input

    float acc0[8] = {0,0,0,0,0,0,0,0};
    float acc1[8] = {0,0,0,0,0,0,0,0};
    float d0 = 0.f, d1 = 0.f;
    float res[8];

    if (deg > 0 || ovf > 0) {
        const float inv_sqrt_h = 0.08838834764831845f;  // 1/sqrt(128)
        const float* qrow = q + (size_t)row * HDIM + hl * 8;
        float4 qa = __ldcs(reinterpret_cast<const float4*>(qrow));
        float4 qb = __ldcs(reinterpret_cast<const float4*>(qrow) + 1);
        qa.x *= inv_sqrt_h; qa.y *= inv_sqrt_h; qa.z *= inv_sqrt_h; qa.w *= inv_sqrt_h;
        qb.x *= inv_sqrt_h; qb.y *= inv_sqrt_h; qb.z *= inv_sqrt_h; qb.w *= inv_sqrt_h;
        float er = g_expl * __half2float(__ldg(g_eh + (size_t)row * EDIM + hl));

        int j = beg;
        for (; j + 4 <= end; j += 4) {
            int j0 = j + half;
            int j1 = j + 2 + half;
            int pk0 = __ldcs(g_bkt + j0);
            int pk1 = __ldcs(g_bkt + j1);
            int c0 = pk0 & 0xFFFFFF, c1 = pk1 & 0xFFFFFF;
            uint4 kr0 = __ldg(reinterpret_cast<const uint4*>(g_kh + (size_t)c0 * HDIM + hl * 8));
            uint4 kr1 = __ldg(reinterpret_cast<const uint4*>(g_kh + (size_t)c1 * HDIM + hl * 8));
            uint4 vr0 = __ldg(reinterpret_cast<const uint4*>(g_vh + (size_t)c0 * HDIM + hl * 8));
            uint4 vr1 = __ldg(reinterpret_cast<const uint4*>(g_vh + (size_t)c1 * HDIM + hl * 8));
            float ec0 = __half2float(__ldg(g_eh + (size_t)c0 * EDIM + hl));
            float ec1 = __half2float(__ldg(g_eh + (size_t)c1 * EDIM + hl));

            float z0 = dot8h(qa, qb, kr0) + er * ec0;
            float z1 = dot8h(qa, qb, kr1) + er * ec1;
            #pragma unroll
            for (int o = 8; o > 0; o >>= 1) {
                z0 += __shfl_xor_sync(0xffffffffu, z0, o);
                z1 += __shfl_xor_sync(0xffffffffu, z1, o);
            }
            float e00 = __expf(z0);
            float e01 = __expf(z1);
            float pw0 = s_pexp[((unsigned)pk0) >> 24];
            float pw1 = s_pexp[((unsigned)pk1) >> 24];
            d0 += e00 + e01;
            d1 += pw0 + pw1;

            float2 v0[4], v1[4];
            v0[0] = __half22float2(*reinterpret_cast<__half2*>(&vr0.x));
            v0[1] = __half22float2(*reinterpret_cast<__half2*>(&vr0.y));
            v0[2] = __half22float2(*reinterpret_cast<__half2*>(&vr0.z));
            v0[3] = __half22float2(*reinterpret_cast<__half2*>(&vr0.w));
            v1[0] = __half22float2(*reinterpret_cast<__half2*>(&vr1.x));
            v1[1] = __half22float2(*reinterpret_cast<__half2*>(&vr1.y));
            v1[2] = __half22float2(*reinterpret_cast<__half2*>(&vr1.z));
            v1[3] = __half22float2(*reinterpret_cast<__half2*>(&vr1.w));
            #pragma unroll
            for (int i = 0; i < 4; i++) {
                acc0[2*i]   += e00 * v0[i].x + e01 * v1[i].x;
                acc0[2*i+1] += e00 * v0[i].y + e01 * v1[i].y;
                acc1[2*i]   += pw0 * v0[i].x + pw1 * v1[i].x;
                acc1[2*i+1] += pw0 * v0[i].y + pw1 * v1[i].y;
            }
        }
        for (; j < end; j += 2) {
            int jj = j + half;
            bool valid = jj < end;
            int pk0 = __ldcs(g_bkt + (valid ? jj : beg));
            int c0 = pk0 & 0xFFFFFF;
            uint4 kr0 = __ldg(reinterpret_cast<const uint4*>(g_kh + (size_t)c0 * HDIM + hl * 8));
            uint4 vr0 = __ldg(reinterpret_cast<const uint4*>(g_vh + (size_t)c0 * HDIM + hl * 8));
            float ec0 = __half2float(__ldg(g_eh + (size_t)c0 * EDIM + hl));
            float z0 = dot8h(qa, qb, kr0) + er * ec0;
            #pragma unroll
            for (int o = 8; o > 0; o >>= 1)
                z0 += __shfl_xor_sync(0xffffffffu, z0, o);
            float e00 = valid ? __expf(z0) : 0.f;
            float pw0 = valid ? s_pexp[((unsigned)pk0) >> 24] : 0.f;
            d0 += e00;
            d1 += pw0;
            float2 v0[4];
            v0[0] = __half22float2(*reinterpret_cast<__half2*>(&vr0.x));
            v0[1] = __half22float2(*reinterpret_cast<__half2*>(&vr0.y));
            v0[2] = __half22float2(*reinterpret_cast<__half2*>(&vr0.z));
            v0[3] = __half22float2(*reinterpret_cast<__half2*>(&vr0.w));
            #pragma unroll
            for (int i = 0; i < 4; i++) {
                acc0[2*i]   += e00 * v0[i].x;
                acc0[2*i+1] += e00 * v0[i].y;
                acc1[2*i]   += pw0 * v0[i].x;
                acc1[2*i+1] += pw0 * v0[i].y;
            }
        }

        // spill entries (only when a row exceeded CAP; never for bench input)
        for (int s = 0; s < ovf; s++) {
            if (g_sp_row[s] != row) continue;
            int pk0 = g_sp_pk[s];
            int c0 = pk0 & 0xFFFFFF;
            uint4 kr0 = __ldg(reinterpret_cast<const uint4*>(g_kh + (size_t)c0 * HDIM + hl * 8));
            uint4 vr0 = __ldg(reinterpret_cast<const uint4*>(g_vh + (size_t)c0 * HDIM + hl * 8));
            float ec0 = __half2float(__ldg(g_eh + (size_t)c0 * EDIM + hl));
            float z0 = dot8h(qa, qb, kr0) + er * ec0;
            #pragma unroll
            for (int o = 8; o > 0; o >>= 1)
                z0 += __shfl_xor_sync(0xffffffffu, z0, o);
            bool act = (half == 0);          // count each spill edge once
            float e00 = act ? __expf(z0) : 0.f;
            float pw0 = act ? s_pexp[((unsigned)pk0) >> 24] : 0.f;
            d0 += e00;
            d1 += pw0;
            float2 v0[4];
            v0[0] = __half22float2(*reinterpret_cast<__half2*>(&vr0.x));
            v0[1] = __half22float2(*reinterpret_cast<__half2*>(&vr0.y));
            v0[2] = __half22float2(*reinterpret_cast<__half2*>(&vr0.z));
            v0[3] = __half22float2(*reinterpret_cast<__half2*>(&vr0.w));
            #pragma unroll
            for (int i = 0; i < 4; i++) {
                acc0[2*i]   += e00 * v0[i].x;
                acc0[2*i+1] += e00 * v0[i].y;
                acc1[2*i]   += pw0 * v0[i].x;
                acc1[2*i+1] += pw0 * v0[i].y;
            }
        }

        // combine halves and normalize
        d0 += __shfl_xor_sync(0xffffffffu, d0, 16);
        d1 += __shfl_xor_sync(0xffffffffu, d1, 16);
        float i0 = (d0 != 0.f) ? 0.5f / d0 : 0.f;
        float i1 = (d1 != 0.f) ? 0.5f / d1 : 0.f;
        #pragma unroll
        for (int i = 0; i < 8; i++) {
            acc0[i] += __shfl_xor_sync(0xffffffffu, acc0[i], 16);
            acc1[i] += __shfl_xor_sync(0xffffffffu, acc1[i], 16);
            res[i] = i0 * acc0[i] + i1 * acc1[i];
        }
    } else {
        #pragma unroll
        for (int i = 0; i < 8; i++) res[i] = 0.f;
    }

    if (half == 0) {
        float4* o = reinterpret_cast<float4*>(out + (size_t)row * HDIM + hl * 8);
        __stcs(o,     make_float4(res[0], res[1], res[2], res[3]));
        __stcs(o + 1, make_float4(res[4], res[5], res[6], res[7]));
    }
}

// ---------------------------------------------------------------------------
extern "C" void kernel_launch(void* const* d_in, const int* in_sizes, int n_in,
                              void* d_out, int out_size) {
    const float* q       = (const float*)d_in[0];
    const float* k       = (const float*)d_in[1];
    const float* v       = (const float*)d_in[2];
    const float* eigs    = (const float*)d_in[3];
    const float* lambda0 = (const float*)d_in[4];
    const float* path_w  = (const float*)d_in[5];
    const int*   indices = (const int*)d_in[6];
    const int*   ptype   = (const int*)d_in[7];
    float*       out     = (float*)d_out;

    int n_edges = in_sizes[6] / 2;
    int n_nodes = in_sizes[0] / HDIM;
    if (n_edges > EDGES)  n_edges = EDGES;
    if (n_nodes > NNODES) n_nodes = NNODES;

    int eb8 = (n_edges / 8 + 255) / 256 + 1;   // scatter blocks
    int rb  = (n_nodes * 32 + 255) / 256;

    k_zero<<<512, 256>>>(lambda0, path_w, n_nodes);
    k_work<<<CONVB + eb8, 256>>>(k, v, eigs, indices, ptype, n_nodes, n_edges);
    k_fused<<<rb, 256>>>(q, out, n_nodes);
}